// round 2
// baseline (speedup 1.0000x reference)
#include <cuda_runtime.h>
#include <cstdint>

#define CB 32
#define CC 256
#define CH 56
#define CW 56
#define HP 58
#define WP 58
#define NPIX (CB*CH*CW)

// ---------------- scratch (device globals; no allocation) ----------------
__device__ __align__(128) int8_t g_xq[CB*HP*WP*CC + 4096];   // padded NHWC ±1/0
__device__ __align__(128) int8_t g_wq[9*CC*CC];              // [tap][o][i] sign
__device__ float  g_alpha[CC];
__device__ __align__(16) int g_acc[(size_t)CB*CH*CW*CC];     // [b][h][w][o] int32
__device__ long long          g_sum[CC];
__device__ unsigned long long g_sumsq[CC];
__device__ float g_scale[CC], g_shift[CC];

// ---------------- helpers ----------------
__device__ __forceinline__ unsigned swz(int row, int c) {
    // 64 rows x 32B tiles; conflict-free for ldmatrix 8-row groups
    return (unsigned)(row * 32 + ((c ^ ((row >> 2) & 1)) * 16));
}
__device__ __forceinline__ void cpa16(unsigned dst, const void* src) {
    asm volatile("cp.async.cg.shared.global [%0], [%1], 16;\n" :: "r"(dst), "l"(src));
}
__device__ __forceinline__ void ldm4(unsigned addr, unsigned &r0, unsigned &r1,
                                     unsigned &r2, unsigned &r3) {
    asm volatile("ldmatrix.sync.aligned.m8n8.x4.shared.b16 {%0,%1,%2,%3}, [%4];\n"
        : "=r"(r0), "=r"(r1), "=r"(r2), "=r"(r3) : "r"(addr));
}
__device__ __forceinline__ void mma8(int* c, const unsigned* a, unsigned b0, unsigned b1) {
    asm volatile("mma.sync.aligned.m16n8k32.row.col.s32.s8.s8.s32 "
        "{%0,%1,%2,%3}, {%4,%5,%6,%7}, {%8,%9}, {%0,%1,%2,%3};\n"
        : "+r"(c[0]), "+r"(c[1]), "+r"(c[2]), "+r"(c[3])
        : "r"(a[0]), "r"(a[1]), "r"(a[2]), "r"(a[3]), "r"(b0), "r"(b1));
}

// ---------------- 1) weight prep ----------------
// wc = clip(w - mean_over_i, -1, 1); alpha[o] = mean|wc|; g_wq = sign(wc)
__global__ void k_prep_weights(const float* __restrict__ w) {
    int o = blockIdx.x, t = threadIdx.x;          // t = input channel i
    __shared__ float red[256];
    const float* wo = w + (size_t)o * CC * 9;
    float wv[9];
    #pragma unroll
    for (int tap = 0; tap < 9; tap++) wv[tap] = wo[t * 9 + tap];
    float absacc = 0.f;
    #pragma unroll
    for (int tap = 0; tap < 9; tap++) {
        red[t] = wv[tap]; __syncthreads();
        for (int s = 128; s > 0; s >>= 1) { if (t < s) red[t] += red[t + s]; __syncthreads(); }
        float m = red[0] * (1.0f / 256.0f);
        __syncthreads();
        float wc = wv[tap] - m;
        wc = fminf(1.f, fmaxf(-1.f, wc));
        absacc += fabsf(wc);
        g_wq[((size_t)tap * CC + o) * CC + t] = (wc >= 0.f) ? (int8_t)1 : (int8_t)-1;
    }
    red[t] = absacc; __syncthreads();
    for (int s = 128; s > 0; s >>= 1) { if (t < s) red[t] += red[t + s]; __syncthreads(); }
    if (t == 0) g_alpha[o] = red[0] * (1.0f / 2304.0f);
}

// ---------------- 2) zero padded activation buffer ----------------
__global__ void k_zero_xq() {
    size_t idx = (size_t)blockIdx.x * blockDim.x + threadIdx.x;
    size_t n = sizeof(g_xq) / 16;
    if (idx < n) ((int4*)g_xq)[idx] = make_int4(0, 0, 0, 0);
}
// ---------------- 3) zero stats ----------------
__global__ void k_zero_stats() {
    int t = threadIdx.x;
    g_sum[t] = 0; g_sumsq[t] = 0;
}

// ---------------- 4) binarize + NCHW->padded NHWC int8 ----------------
__global__ void k_pack(const float* __restrict__ x) {
    // grid: (CB*CH, 8); block 256
    int bh = blockIdx.x; int b = bh / CH, h = bh % CH;
    int ic = blockIdx.y;                                  // 32-channel chunk
    __shared__ int8_t tile[32][65];
    int tx = threadIdx.x & 31, ty = threadIdx.x >> 5;     // ty 0..7
    const float* xp = x + (((size_t)(b * CC + ic * 32) * CH) + h) * CW;
    #pragma unroll
    for (int ii = 0; ii < 4; ii++) {
        int il = ty * 4 + ii;
        const float* row = xp + (size_t)il * CH * CW;
        #pragma unroll
        for (int wc2 = 0; wc2 < 2; wc2++) {
            int w = wc2 * 32 + tx;
            if (w < CW) tile[il][w] = (row[w] >= 0.f) ? (int8_t)1 : (int8_t)-1;
        }
    }
    __syncthreads();
    int8_t* dst0 = g_xq + ((size_t)(b * HP + h + 1) * WP + 1) * CC + ic * 32 + tx;
    for (int w = ty; w < CW; w += 8)
        dst0[(size_t)w * CC] = tile[tx][w];
}

// ---------------- 5) conv: IMMA implicit GEMM ----------------
// CTA = (b,h): M=64 spatial (w), N=256 cout, K = 9 taps * 256 cin.
__global__ void __launch_bounds__(256) k_conv() {
    __shared__ __align__(128) int8_t sA[2][64 * 32];
    __shared__ __align__(128) int8_t sB[2][256 * 32];
    int bh = blockIdx.x;
    int b = bh / CH, h = bh % CH;
    int tid = threadIdx.x;
    int lane = tid & 31, warp = tid >> 5;
    int g = lane >> 2, t4 = lane & 3;
    int n0w = warp * 32;

    unsigned sAbase = (unsigned)__cvta_generic_to_shared(&sA[0][0]);
    unsigned sBbase = (unsigned)__cvta_generic_to_shared(&sB[0][0]);

    // cp.async assignments: A (t<128): row=t>>1, chunk=t&1; B: row=t, both chunks
    int arow = tid >> 1, ac = tid & 1;
    const int8_t* gA0 = g_xq + ((size_t)(b * HP + h) * WP + arow) * CC + ac * 16;
    unsigned sAdst = sAbase + swz(arow, ac);
    const int8_t* gB0 = g_wq + (size_t)tid * CC;
    unsigned sBdst0 = sBbase + swz(tid, 0);
    unsigned sBdst1 = sBbase + swz(tid, 1);

    // ldmatrix base offsets (per-thread)
    unsigned aoff = sAbase + swz(lane & 15, lane >> 4);
    unsigned boff = sBbase + swz(n0w + (lane & 15), lane >> 4);

    int acc[4][4][4];
    #pragma unroll
    for (int i = 0; i < 4; i++)
        #pragma unroll
        for (int j = 0; j < 4; j++)
            #pragma unroll
            for (int k = 0; k < 4; k++) acc[i][j][k] = 0;

    auto load_stage = [&](int ks, int buf) {
        int tap = ks >> 3, kk = ks & 7;
        int dh = tap / 3, dw = tap - dh * 3;
        if (tid < 128)
            cpa16(sAdst + buf * 2048, gA0 + ((size_t)(dh * WP + dw)) * CC + kk * 32);
        const int8_t* gb = gB0 + (size_t)tap * CC * CC + kk * 32;
        cpa16(sBdst0 + buf * 8192, gb);
        cpa16(sBdst1 + buf * 8192, gb + 16);
        asm volatile("cp.async.commit_group;\n");
    };

    load_stage(0, 0);
    for (int ks = 0; ks < 72; ks++) {
        int buf = ks & 1;
        if (ks + 1 < 72) {
            load_stage(ks + 1, buf ^ 1);
            asm volatile("cp.async.wait_group 1;\n");
        } else {
            asm volatile("cp.async.wait_group 0;\n");
        }
        __syncthreads();

        unsigned ab = aoff + buf * 2048;
        unsigned bb = boff + buf * 8192;
        unsigned bf0[4], bf1[4];
        ldm4(bb,        bf0[0], bf0[1], bf0[2], bf0[3]);  // ntiles 0,1
        ldm4(bb + 512,  bf1[0], bf1[1], bf1[2], bf1[3]);  // ntiles 2,3
        #pragma unroll
        for (int mt = 0; mt < 4; mt++) {
            unsigned af[4];
            ldm4(ab + mt * 512, af[0], af[1], af[2], af[3]);
            mma8(acc[mt][0], af, bf0[0], bf0[2]);
            mma8(acc[mt][1], af, bf0[1], bf0[3]);
            mma8(acc[mt][2], af, bf1[0], bf1[2]);
            mma8(acc[mt][3], af, bf1[1], bf1[3]);
        }
        __syncthreads();
    }

    // epilogue: store acc [b][h][w][o] + per-channel sum / sumsq
    int* accbase = g_acc + (size_t)bh * CW * CC;
    #pragma unroll
    for (int nt = 0; nt < 4; nt++) {
        int n = n0w + nt * 8 + t4 * 2;
        int s0 = 0, s1 = 0;
        unsigned q0 = 0, q1 = 0;
        #pragma unroll
        for (int mt = 0; mt < 4; mt++) {
            int m1 = mt * 16 + g, m2 = m1 + 8;
            int c0 = acc[mt][nt][0], c1 = acc[mt][nt][1];
            int c2 = acc[mt][nt][2], c3 = acc[mt][nt][3];
            if (m1 < CW) {
                *(int2*)(accbase + (size_t)m1 * CC + n) = make_int2(c0, c1);
                s0 += c0; q0 += (unsigned)(c0 * c0);
                s1 += c1; q1 += (unsigned)(c1 * c1);
            }
            if (m2 < CW) {
                *(int2*)(accbase + (size_t)m2 * CC + n) = make_int2(c2, c3);
                s0 += c2; q0 += (unsigned)(c2 * c2);
                s1 += c3; q1 += (unsigned)(c3 * c3);
            }
        }
        #pragma unroll
        for (int off = 4; off < 32; off <<= 1) {
            s0 += __shfl_xor_sync(0xffffffffu, s0, off);
            s1 += __shfl_xor_sync(0xffffffffu, s1, off);
            q0 += __shfl_xor_sync(0xffffffffu, q0, off);
            q1 += __shfl_xor_sync(0xffffffffu, q1, off);
        }
        if (g == 0) {
            atomicAdd((unsigned long long*)&g_sum[n],     (unsigned long long)(long long)s0);
            atomicAdd((unsigned long long*)&g_sum[n + 1], (unsigned long long)(long long)s1);
            atomicAdd(&g_sumsq[n],     (unsigned long long)q0);
            atomicAdd(&g_sumsq[n + 1], (unsigned long long)q1);
        }
    }
}

// ---------------- 6) per-channel scale/shift ----------------
__global__ void k_finalize(const float* __restrict__ gamma, const float* __restrict__ beta) {
    int o = threadIdx.x;
    double N = (double)NPIX;
    double mean = (double)g_sum[o] / N;
    double ex2  = (double)g_sumsq[o] / N;
    double var  = ex2 - mean * mean;
    double a    = (double)g_alpha[o];
    double inv  = 1.0 / sqrt(a * a * var + 1e-5);
    double sc   = (double)gamma[o] * a * inv;
    g_scale[o] = (float)sc;
    g_shift[o] = (float)((double)beta[o] - sc * mean);
}

// ---------------- 7) affine + relu + NHWC->NCHW ----------------
__global__ void k_epilogue(float* __restrict__ out) {
    __shared__ float tile[64][57];
    int bh = blockIdx.x, oc = blockIdx.y;
    int b = bh / CH, h = bh % CH;
    const int* accp = g_acc + (size_t)bh * CW * CC + oc * 64;
    int t = threadIdx.x;
    int ol = t & 63, wq = t >> 6;
    float sc = g_scale[oc * 64 + ol], sh = g_shift[oc * 64 + ol];
    for (int w = wq; w < CW; w += 4)
        tile[ol][w] = fmaxf(fmaf(sc, (float)accp[(size_t)w * CC + ol], sh), 0.f);
    __syncthreads();
    float* op = out + ((size_t)(b * CC + oc * 64) * CH + h) * CW;
    for (int idx = t; idx < 64 * CW; idx += 256) {
        int o_l = idx / CW, w = idx - o_l * CW;
        op[(size_t)o_l * CH * CW + w] = tile[o_l][w];
    }
}

// ---------------- launch ----------------
extern "C" void kernel_launch(void* const* d_in, const int* in_sizes, int n_in,
                              void* d_out, int out_size) {
    (void)in_sizes; (void)n_in; (void)out_size;
    const float* x     = (const float*)d_in[0];
    const float* w     = (const float*)d_in[1];
    // d_in[2] = bias: cancels exactly under training-mode BN
    const float* gamma = (const float*)d_in[3];
    const float* beta  = (const float*)d_in[4];
    float* out = (float*)d_out;

    k_prep_weights<<<CC, 256>>>(w);
    k_zero_xq<<<(int)((sizeof(g_xq) / 16 + 255) / 256), 256>>>();
    k_zero_stats<<<1, 256>>>();
    k_pack<<<dim3(CB * CH, 8), 256>>>(x);
    k_conv<<<CB * CH, 256>>>();
    k_finalize<<<1, 256>>>(gamma, beta);
    k_epilogue<<<dim3(CB * CH, 4), 256>>>(out);
}